// round 16
// baseline (speedup 1.0000x reference)
#include <cuda_runtime.h>
#include <math.h>
#include <stdint.h>

#define Nn 50000
#define Ee 250000
#define Bb 128
#define Dd 302
#define Qq 600
#define Cc 2000
#define NEG_SLOPE 0.2f

// ---------------- scratch (device globals; no allocation allowed) ----------
__device__ float    g_h[(size_t)Nn * Dd];   // GEMM output (pre-aggregation h)
__device__ uint32_t g_op[(size_t)Nn * Dd];  // packed (hi,lo) GEMM input
__device__ uint32_t g_wp[Dd * Dd];          // packed theta
__device__ float    g_o[(size_t)Nn * Dd];   // layer-3 fp32 output (pooling)
__device__ float    g_as[Nn], g_ad[Nn], g_s[Nn];
__device__ float    g_asp[3][Nn], g_adp[3][Nn];
__device__ int      g_cnt[Nn];
__device__ int      g_cur[Nn];
__device__ int      g_rowptr[Nn + 1];
__device__ int      g_bsum[256];
__device__ int      g_csrc[Ee + Nn];
__device__ float    g_qp[Bb * Dd];
__device__ float    g_pool[Bb * Dd];

// ---------------- helpers ---------------------------------------------------
__device__ __forceinline__ float lrelu(float x) { return x > 0.f ? x : NEG_SLOPE * x; }

__device__ __forceinline__ int lower_bound_i(const int* a, int n, int v) {
    int lo = 0, hi = n;
    while (lo < hi) { int m = (lo + hi) >> 1; if (a[m] < v) lo = m + 1; else hi = m; }
    return lo;
}

// pack two fp32 -> bf16x2 (e0 in lower 16, e1 in upper 16), round-to-nearest
__device__ __forceinline__ uint32_t packbf(float e0, float e1) {
    uint32_t r;
    asm("cvt.rn.bf16x2.f32 %0, %1, %2;" : "=r"(r) : "f"(e1), "f"(e0));
    return r;
}
// one element -> packed word: bits[31:16] = bf16(hi), bits[15:0] = bf16(lo)
__device__ __forceinline__ uint32_t packsplit(float v) {
    uint32_t h2 = packbf(v, 0.f);               // bf16(v) in lower 16
    float hf = __uint_as_float(h2 << 16);       // exact fp32 of hi
    uint32_t l2 = packbf(v - hf, 0.f);          // bf16 of residual
    return (h2 << 16) | (l2 & 0xffffu);
}

#define MMA_BF16(cr, a, b) \
    asm volatile("mma.sync.aligned.m16n8k16.row.col.f32.bf16.bf16.f32 " \
        "{%0,%1,%2,%3}, {%4,%5,%6,%7}, {%8,%9}, {%0,%1,%2,%3};" \
        : "+f"((cr)[0]), "+f"((cr)[1]), "+f"((cr)[2]), "+f"((cr)[3]) \
        : "r"((a)[0]), "r"((a)[1]), "r"((a)[2]), "r"((a)[3]), \
          "r"((b)[0]), "r"((b)[1]))

#define CP_ASYNC8(dst_smem, src_ptr, sz) \
    asm volatile("cp.async.ca.shared.global [%0], [%1], 8, %2;" \
        :: "r"(dst_smem), "l"(src_ptr), "r"(sz))
#define CP_COMMIT() asm volatile("cp.async.commit_group;" ::: "memory")
#define CP_WAIT0()  asm volatile("cp.async.wait_group 0;" ::: "memory")

// ---------------- pack x and theta into (hi,lo) words ------------------------
__global__ void pack_all_k(const float* __restrict__ th, const float* __restrict__ x) {
    int i = blockIdx.x * blockDim.x + threadIdx.x;
    if (i < Dd * Dd) g_wp[i] = packsplit(th[i]);
    int j = i - Dd * Dd;
    if (j >= 0 && j < Nn * Dd) g_op[j] = packsplit(x[j]);
}

// ---------------- CSR build --------------------------------------------------
__global__ void zero_k() {
    int i = blockIdx.x * blockDim.x + threadIdx.x;
    if (i < Nn) { g_cnt[i] = 0; g_cur[i] = 0; }
}

__global__ void count_k(const int* __restrict__ edges) {
    int i = blockIdx.x * blockDim.x + threadIdx.x;
    if (i >= Ee + Nn) return;
    int dst = (i < Ee) ? edges[Ee + i] : (i - Ee);
    atomicAdd(&g_cnt[dst], 1);
}

__global__ void scan1_k() {
    __shared__ int sh[256];
    int tid = threadIdx.x;
    int i = blockIdx.x * 256 + tid;
    int v = (i < Nn) ? g_cnt[i] : 0;
    sh[tid] = v;
    __syncthreads();
    #pragma unroll
    for (int off = 1; off < 256; off <<= 1) {
        int t = (tid >= off) ? sh[tid - off] : 0;
        __syncthreads();
        sh[tid] += t;
        __syncthreads();
    }
    if (i <= Nn) g_rowptr[i] = sh[tid] - v;
    if (tid == 255) g_bsum[blockIdx.x] = sh[255];
}

__global__ void scan2_k(int nblk) {
    __shared__ int sh[256];
    int tid = threadIdx.x;
    int v = (tid < nblk) ? g_bsum[tid] : 0;
    sh[tid] = v;
    __syncthreads();
    #pragma unroll
    for (int off = 1; off < 256; off <<= 1) {
        int t = (tid >= off) ? sh[tid - off] : 0;
        __syncthreads();
        sh[tid] += t;
        __syncthreads();
    }
    if (tid < nblk) g_bsum[tid] = sh[tid] - v;
    if (tid == 255) g_rowptr[Nn] = sh[255];
}

__global__ void scan3_k() {
    int i = blockIdx.x * 256 + threadIdx.x;
    if (i < Nn) g_rowptr[i] += g_bsum[blockIdx.x];
}

__global__ void fill_k(const int* __restrict__ edges) {
    int i = blockIdx.x * blockDim.x + threadIdx.x;
    if (i >= Ee + Nn) return;
    int src, dst;
    if (i < Ee) { src = edges[i]; dst = edges[Ee + i]; }
    else        { src = dst = i - Ee; }
    int p = g_rowptr[dst] + atomicAdd(&g_cur[dst], 1);
    g_csrc[p] = src;
}

// ---------------- bf16 split mma GEMM, packed (hi,lo) inputs ----------------
// C[M,302] = A @ theta^T, A/theta given as packed hi/lo words. CTA tile
// 128x128x16, cp.async double-buffered, 48KB static smem (2 CTA/SM).
// 8 warps = 2(m) x 4(n); warp tile 64x32. m16n8k16, 3-term split.
// Fragment path: LDS.64 -> 2x PRMT -> MMA. Fully-OOB n-warps skip MMA.
// Epilogue fuses attention dots (aliased smem).
#define BMt 128
#define BNt 128
#define BKt 16
#define SWd 24
#define NIT 19              // ceil(302/16)
#define STGF (BMt * SWd)    // 3072 words per stage buffer

__global__ __launch_bounds__(256, 2) void gemm_mma_k(const uint32_t* __restrict__ A,
                                                     const uint32_t* __restrict__ W,
                                                     float* __restrict__ C,
                                                     const float* __restrict__ att_s,
                                                     const float* __restrict__ att_d) {
    __shared__ uint32_t pool[4 * STGF];   // 49152 B; epilogue aliases
    uint32_t* SA = pool;                  // [2][STGF]
    uint32_t* SW = pool + 2 * STGF;       // [2][STGF]

    int tid = threadIdx.x;
    int wid = tid >> 5, lane = tid & 31;
    int g = lane >> 2, t = lane & 3;
    int m0 = blockIdx.y * BMt, n0 = blockIdx.x * BNt;
    int wm = (wid >> 2) * 64;
    int wn = (wid & 3) * 32;
    const bool active = (n0 + wn) < Dd;   // warp-uniform column validity

    float c[4][4][4];
    #pragma unroll
    for (int i = 0; i < 4; i++)
        #pragma unroll
        for (int j = 0; j < 4; j++)
            #pragma unroll
            for (int f = 0; f < 4; f++) c[i][j][f] = 0.f;

    int srow = tid >> 3;   // 0..31
    int sc2  = tid & 7;    // word-pair column index (k offset = 2*sc2)

    auto stage = [&](int s, int k0) {
        #pragma unroll
        for (int e = 0; e < 4; e++) {
            int row = srow + e * 32;
            int gm = m0 + row, gk = k0 + 2 * sc2;
            bool ok = (gm < Nn) && (gk < Dd);
            const uint32_t* src = ok ? (A + (size_t)gm * Dd + gk) : A;
            uint32_t dst = (uint32_t)__cvta_generic_to_shared(&SA[s * STGF + row * SWd + 2 * sc2]);
            CP_ASYNC8(dst, src, ok ? 8u : 0u);
        }
        #pragma unroll
        for (int e = 0; e < 4; e++) {
            int row = srow + e * 32;
            int gn = n0 + row, gk = k0 + 2 * sc2;
            bool ok = (gn < Dd) && (gk < Dd);
            const uint32_t* src = ok ? (W + (size_t)gn * Dd + gk) : W;
            uint32_t dst = (uint32_t)__cvta_generic_to_shared(&SW[s * STGF + row * SWd + 2 * sc2]);
            CP_ASYNC8(dst, src, ok ? 8u : 0u);
        }
    };

    stage(0, 0);
    CP_COMMIT();

    for (int it = 0; it < NIT; it++) {
        CP_WAIT0();
        __syncthreads();
        if (it + 1 < NIT) {
            stage((it + 1) & 1, (it + 1) * BKt);
            CP_COMMIT();
        }

        if (active) {
            const uint32_t* sa = SA + (it & 1) * STGF;
            const uint32_t* sw = SW + (it & 1) * STGF;

            uint32_t bh[4][2], bl[4][2];
            #pragma unroll
            for (int nt = 0; nt < 4; nt++) {
                int nr = wn + nt * 8 + g;
                uint2 b0 = *(const uint2*)&sw[nr * SWd + 2 * t];
                uint2 b1 = *(const uint2*)&sw[nr * SWd + 2 * t + 8];
                bh[nt][0] = __byte_perm(b0.x, b0.y, 0x7632);
                bl[nt][0] = __byte_perm(b0.x, b0.y, 0x5410);
                bh[nt][1] = __byte_perm(b1.x, b1.y, 0x7632);
                bl[nt][1] = __byte_perm(b1.x, b1.y, 0x5410);
            }
            #pragma unroll
            for (int mt = 0; mt < 4; mt++) {
                int mr = wm + mt * 16 + g;
                uint2 A0 = *(const uint2*)&sa[mr * SWd + 2 * t];
                uint2 A1 = *(const uint2*)&sa[(mr + 8) * SWd + 2 * t];
                uint2 A2 = *(const uint2*)&sa[mr * SWd + 2 * t + 8];
                uint2 A3 = *(const uint2*)&sa[(mr + 8) * SWd + 2 * t + 8];
                uint32_t ah[4], al[4];
                ah[0] = __byte_perm(A0.x, A0.y, 0x7632);
                al[0] = __byte_perm(A0.x, A0.y, 0x5410);
                ah[1] = __byte_perm(A1.x, A1.y, 0x7632);
                al[1] = __byte_perm(A1.x, A1.y, 0x5410);
                ah[2] = __byte_perm(A2.x, A2.y, 0x7632);
                al[2] = __byte_perm(A2.x, A2.y, 0x5410);
                ah[3] = __byte_perm(A3.x, A3.y, 0x7632);
                al[3] = __byte_perm(A3.x, A3.y, 0x5410);
                #pragma unroll
                for (int nt = 0; nt < 4; nt++) {
                    MMA_BF16(c[mt][nt], ah, bh[nt]);
                    MMA_BF16(c[mt][nt], ah, bl[nt]);
                    MMA_BF16(c[mt][nt], al, bh[nt]);
                }
            }
        }
    }

    // epilogue: alias the stage buffers for attention vectors + partial sums
    __syncthreads();
    float* s_as  = (float*)pool;             // [128]
    float* s_ad  = (float*)pool + 128;       // [128]
    float* s_pas = (float*)pool + 256;       // [512]
    float* s_pad = (float*)pool + 768;       // [512]
    if (tid < 128) {
        int cidx = n0 + tid;
        s_as[tid] = (cidx < Dd) ? att_s[cidx] : 0.f;
        s_ad[tid] = (cidx < Dd) ? att_d[cidx] : 0.f;
    }
    __syncthreads();

    #pragma unroll
    for (int mt = 0; mt < 4; mt++) {
        int row = m0 + wm + mt * 16 + g;
        float ps = 0.f, pd = 0.f, qs = 0.f, qd = 0.f;
        #pragma unroll
        for (int nt = 0; nt < 4; nt++) {
            int cn = wn + nt * 8 + 2 * t;       // local col in [0,128)
            int col = n0 + cn;
            if (col < Dd) {
                if (row < Nn)
                    *(float2*)(C + (size_t)row * Dd + col) =
                        make_float2(c[mt][nt][0], c[mt][nt][1]);
                if (row + 8 < Nn)
                    *(float2*)(C + (size_t)(row + 8) * Dd + col) =
                        make_float2(c[mt][nt][2], c[mt][nt][3]);
            }
            float a0 = s_as[cn], a1 = s_as[cn + 1];
            float d0 = s_ad[cn], d1 = s_ad[cn + 1];
            ps += c[mt][nt][0] * a0 + c[mt][nt][1] * a1;
            pd += c[mt][nt][0] * d0 + c[mt][nt][1] * d1;
            qs += c[mt][nt][2] * a0 + c[mt][nt][3] * a1;
            qd += c[mt][nt][2] * d0 + c[mt][nt][3] * d1;
        }
        #pragma unroll
        for (int o = 1; o <= 2; o <<= 1) {
            ps += __shfl_xor_sync(0xffffffffu, ps, o);
            pd += __shfl_xor_sync(0xffffffffu, pd, o);
            qs += __shfl_xor_sync(0xffffffffu, qs, o);
            qd += __shfl_xor_sync(0xffffffffu, qd, o);
        }
        if (t == 0) {
            int i1 = wm + mt * 16 + g;
            int nw = wid & 3;
            s_pas[nw * 128 + i1] = ps;  s_pad[nw * 128 + i1] = pd;
            s_pas[nw * 128 + i1 + 8] = qs;  s_pad[nw * 128 + i1 + 8] = qd;
        }
    }
    __syncthreads();
    if (tid < 128) {
        int row = m0 + tid;
        if (row < Nn)
            g_asp[blockIdx.x][row] = s_pas[tid] + s_pas[128 + tid] +
                                     s_pas[256 + tid] + s_pas[384 + tid];
    } else {
        int i = tid - 128;
        int row = m0 + i;
        if (row < Nn)
            g_adp[blockIdx.x][row] = s_pad[i] + s_pad[128 + i] +
                                     s_pad[256 + i] + s_pad[384 + i];
    }
}

__global__ void combine_k() {
    int i = blockIdx.x * blockDim.x + threadIdx.x;
    if (i < Nn) {
        g_as[i] = g_asp[0][i] + g_asp[1][i] + g_asp[2][i];
        g_ad[i] = g_adp[0][i] + g_adp[1][i] + g_adp[2][i];
    }
}

// ---------------- fused edge softmax + aggregation (warp per dst) -----------
// mode 0: write packed (hi,lo) output for next GEMM.
// mode 1: write fp32 output + fused pooling score g_s.
__global__ void agg_k(const float* __restrict__ h,
                      const float* __restrict__ bias,
                      uint32_t* __restrict__ opk,
                      float* __restrict__ ofp,
                      const int* __restrict__ batch, int mode) {
    int w = (blockIdx.x * blockDim.x + threadIdx.x) >> 5;
    int lane = threadIdx.x & 31;
    if (w >= Nn) return;
    int beg = g_rowptr[w], end = g_rowptr[w + 1];
    float ad = g_ad[w];

    float m = -3.4e38f, den = 0.f;
    for (int j = beg + lane; j < end; j += 32) {
        float e = lrelu(g_as[g_csrc[j]] + ad);
        if (e > m) { den = den * __expf(m - e) + 1.f; m = e; }
        else den += __expf(e - m);
    }
    #pragma unroll
    for (int o = 16; o; o >>= 1) {
        float mo = __shfl_xor_sync(0xffffffffu, m, o);
        float eo = __shfl_xor_sync(0xffffffffu, den, o);
        float mn = fmaxf(m, mo);
        den = den * __expf(m - mn) + eo * __expf(mo - mn);
        m = mn;
    }
    float inv = 1.f / den;

    float acc[10];
    #pragma unroll
    for (int i = 0; i < 10; i++) acc[i] = 0.f;

    for (int base = beg; base < end; base += 32) {
        int j = base + lane;
        float wt = 0.f; int src = 0;
        if (j < end) {
            src = g_csrc[j];
            wt = __expf(lrelu(g_as[src] + ad) - m) * inv;
        }
        int cnt = min(32, end - base);
        for (int u = 0; u < cnt; u++) {
            float wu = __shfl_sync(0xffffffffu, wt, u);
            int   su = __shfl_sync(0xffffffffu, src, u);
            const float* hr = h + (size_t)su * Dd;
            #pragma unroll
            for (int i = 0; i < 9; i++) acc[i] += wu * hr[lane + i * 32];
            int cc = lane + 288;
            if (cc < Dd) acc[9] += wu * hr[cc];
        }
    }

    if (mode == 0) {
        #pragma unroll
        for (int i = 0; i < 10; i++) {
            int cc = lane + i * 32;
            if (cc < Dd) {
                float v = acc[i] + bias[cc];
                v = v > 0.f ? v : 0.f;
                opk[(size_t)w * Dd + cc] = packsplit(v);
            }
        }
    } else {
        int b = batch[w];
        const float* qr = g_qp + b * Dd;
        float s = 0.f;
        #pragma unroll
        for (int i = 0; i < 10; i++) {
            int cc = lane + i * 32;
            if (cc < Dd) {
                float v = acc[i] + bias[cc];
                v = v > 0.f ? v : 0.f;
                ofp[(size_t)w * Dd + cc] = v;
                s += v * qr[cc];
            }
        }
        #pragma unroll
        for (int o = 16; o; o >>= 1) s += __shfl_xor_sync(0xffffffffu, s, o);
        if (lane == 0) g_s[w] = s * 0.04082482904638630f;  // 1/sqrt(600)
    }
}

// ---------------- qp = query @ attW  [B,D] ----------------------------------
__global__ void qp_k(const float* __restrict__ query, const float* __restrict__ attW) {
    int b = blockIdx.x;
    __shared__ float q[Qq];
    for (int i = threadIdx.x; i < Qq; i += blockDim.x) q[i] = query[(size_t)b * Qq + i];
    __syncthreads();
    for (int d = threadIdx.x; d < Dd; d += blockDim.x) {
        float acc = 0.f;
        for (int qi = 0; qi < Qq; qi++) acc += q[qi] * attW[(size_t)qi * Dd + d];
        g_qp[b * Dd + d] = acc;
    }
}

// ---------------- block-per-graph softmax pooling (batch is sorted) ---------
__global__ __launch_bounds__(256) void pool_k(const float* __restrict__ h,
                                              const int* __restrict__ batch) {
    int b = blockIdx.x;
    int tid = threadIdx.x, wid = tid >> 5, lane = tid & 31;
    __shared__ float red[256];
    __shared__ float s_acc[8][304];
    int start = lower_bound_i(batch, Nn, b);
    int end   = lower_bound_i(batch, Nn, b + 1);

    float m = -3.4e38f;
    for (int n = start + tid; n < end; n += 256) m = fmaxf(m, g_s[n]);
    red[tid] = m; __syncthreads();
    for (int o = 128; o; o >>= 1) { if (tid < o) red[tid] = fmaxf(red[tid], red[tid + o]); __syncthreads(); }
    m = red[0]; __syncthreads();

    float ds = 0.f;
    for (int n = start + tid; n < end; n += 256) ds += __expf(g_s[n] - m);
    red[tid] = ds; __syncthreads();
    for (int o = 128; o; o >>= 1) { if (tid < o) red[tid] += red[tid + o]; __syncthreads(); }
    float total = red[0];
    float inv = (total > 0.f) ? 1.f / total : 0.f;
    __syncthreads();

    float acc[10];
    #pragma unroll
    for (int i = 0; i < 10; i++) acc[i] = 0.f;
    for (int r = start + wid; r < end; r += 8) {
        float wt = __expf(g_s[r] - m) * inv;
        const float* hr = h + (size_t)r * Dd;
        #pragma unroll
        for (int i = 0; i < 9; i++) acc[i] += wt * hr[lane + i * 32];
        int cc = lane + 288;
        if (cc < Dd) acc[9] += wt * hr[cc];
    }
    #pragma unroll
    for (int i = 0; i < 10; i++) {
        int cc = lane + i * 32;
        if (cc < Dd) s_acc[wid][cc] = acc[i];
    }
    __syncthreads();
    for (int cc = tid; cc < Dd; cc += 256) {
        float v = 0.f;
        #pragma unroll
        for (int u = 0; u < 8; u++) v += s_acc[u][cc];
        g_pool[b * Dd + cc] = v > 0.f ? v : 0.f;   // ReLU fused
    }
}

// ---------------- final: out = relu(pooled) @ lin_w^T + lin_b ---------------
#define FINAL_SMEM (128 * 303 * 4)
__global__ __launch_bounds__(512) void final_k(const float* __restrict__ lin_w,
                                               const float* __restrict__ lin_b,
                                               float* __restrict__ out) {
    extern __shared__ float ps[];   // [128][303]
    int tid = threadIdx.x;
    for (int i = tid; i < Bb * Dd; i += 512) {
        int bb = i / Dd, k = i - bb * Dd;
        ps[bb * 303 + k] = g_pool[i];
    }
    __syncthreads();
    int w = tid >> 5, lane = tid & 31;
    int c = blockIdx.x * 16 + w;
    const float* wr = lin_w + (size_t)c * Dd;
    float a0 = 0.f, a1 = 0.f, a2 = 0.f, a3 = 0.f;
    for (int k = 0; k < Dd; k++) {
        float wv = wr[k];
        a0 += wv * ps[lane * 303 + k];
        a1 += wv * ps[(lane + 32) * 303 + k];
        a2 += wv * ps[(lane + 64) * 303 + k];
        a3 += wv * ps[(lane + 96) * 303 + k];
    }
    float lb = lin_b[c];
    out[(size_t)lane * Cc + c]        = a0 + lb;
    out[(size_t)(lane + 32) * Cc + c] = a1 + lb;
    out[(size_t)(lane + 64) * Cc + c] = a2 + lb;
    out[(size_t)(lane + 96) * Cc + c] = a3 + lb;
}

// ---------------- launch -----------------------------------------------------
extern "C" void kernel_launch(void* const* d_in, const int* in_sizes, int n_in,
                              void* d_out, int out_size) {
    const float* x        = (const float*)d_in[0];
    const int*   edges    = (const int*)  d_in[1];
    const float* query    = (const float*)d_in[2];
    const int*   batch    = (const int*)  d_in[3];
    const float* theta    = (const float*)d_in[4];
    const float* att_src  = (const float*)d_in[5];
    const float* att_dst  = (const float*)d_in[6];
    const float* gat_bias = (const float*)d_in[7];
    const float* attW     = (const float*)d_in[8];
    const float* lin_w    = (const float*)d_in[9];
    const float* lin_b    = (const float*)d_in[10];
    float* out = (float*)d_out;

    float *p_h, *p_o;
    uint32_t *p_op, *p_wp;
    cudaGetSymbolAddress((void**)&p_h, g_h);
    cudaGetSymbolAddress((void**)&p_o, g_o);
    cudaGetSymbolAddress((void**)&p_op, g_op);
    cudaGetSymbolAddress((void**)&p_wp, g_wp);

    cudaFuncSetAttribute(final_k, cudaFuncAttributeMaxDynamicSharedMemorySize, FINAL_SMEM);

    dim3 ggrid((Dd + BNt - 1) / BNt, (Nn + BMt - 1) / BMt);
    int wgrid = (Nn * 32 + 255) / 256;
    int cgrid = (Nn + 255) / 256;
    int sblk = (Nn + 255) / 256;

    // pack inputs + CSR build (parallel scan)
    pack_all_k<<<(Dd * Dd + Nn * Dd + 255) / 256, 256>>>(theta, x);
    zero_k<<<cgrid, 256>>>();
    count_k<<<(Ee + Nn + 255) / 256, 256>>>(edges);
    scan1_k<<<sblk, 256>>>();
    scan2_k<<<1, 256>>>(sblk);
    scan3_k<<<sblk, 256>>>();
    fill_k<<<(Ee + Nn + 255) / 256, 256>>>(edges);

    // layer 1 (input = packed x in g_op)
    gemm_mma_k<<<ggrid, 256>>>(p_op, p_wp, p_h, att_src, att_dst);
    combine_k<<<cgrid, 256>>>();
    agg_k<<<wgrid, 256>>>(p_h, gat_bias, p_op, p_o, batch, 0);
    // layer 2
    gemm_mma_k<<<ggrid, 256>>>(p_op, p_wp, p_h, att_src, att_dst);
    combine_k<<<cgrid, 256>>>();
    agg_k<<<wgrid, 256>>>(p_h, gat_bias, p_op, p_o, batch, 0);
    // layer 3 (fuses pooling score)
    gemm_mma_k<<<ggrid, 256>>>(p_op, p_wp, p_h, att_src, att_dst);
    combine_k<<<cgrid, 256>>>();
    qp_k<<<Bb, 384>>>(query, attW);
    agg_k<<<wgrid, 256>>>(p_h, gat_bias, p_op, p_o, batch, 1);

    pool_k<<<Bb, 256>>>(p_o, batch);
    final_k<<<Cc / 16, 512, FINAL_SMEM>>>(lin_w, lin_b, out);
}

// round 17
// speedup vs baseline: 1.0739x; 1.0739x over previous
#include <cuda_runtime.h>
#include <math.h>
#include <stdint.h>

#define Nn 50000
#define Ee 250000
#define Bb 128
#define Dd 302
#define HS 304               // padded row stride for h/o/qp (16B-aligned rows)
#define Qq 600
#define Cc 2000
#define NEG_SLOPE 0.2f

// ---------------- scratch (device globals; no allocation allowed) ----------
__device__ float g_h[(size_t)Nn * HS];     // GEMM output (stride HS)
__device__ float g_o[(size_t)Nn * HS];     // agg output (stride HS)
__device__ float g_as[Nn], g_ad[Nn], g_s[Nn];
__device__ float g_asp[3][Nn], g_adp[3][Nn];
__device__ int   g_cnt[Nn];
__device__ int   g_cur[Nn];
__device__ int   g_rowptr[Nn + 1];
__device__ int   g_bsum[256];
__device__ int   g_csrc[Ee + Nn];
__device__ float g_qp[Bb * HS];
__device__ float g_pool[Bb * Dd];

// ---------------- helpers ---------------------------------------------------
__device__ __forceinline__ float lrelu(float x) { return x > 0.f ? x : NEG_SLOPE * x; }

__device__ __forceinline__ int lower_bound_i(const int* a, int n, int v) {
    int lo = 0, hi = n;
    while (lo < hi) { int m = (lo + hi) >> 1; if (a[m] < v) lo = m + 1; else hi = m; }
    return lo;
}

// pack two fp32 -> bf16x2 (e0 in lower 16, e1 in upper 16)
__device__ __forceinline__ uint32_t packbf(float e0, float e1) {
    uint32_t r;
    asm("cvt.rn.bf16x2.f32 %0, %1, %2;" : "=r"(r) : "f"(e1), "f"(e0));
    return r;
}
__device__ __forceinline__ float bflo(uint32_t r) { return __uint_as_float(r << 16); }
__device__ __forceinline__ float bfhi(uint32_t r) { return __uint_as_float(r & 0xffff0000u); }

#define MMA_BF16(cr, a, b) \
    asm volatile("mma.sync.aligned.m16n8k16.row.col.f32.bf16.bf16.f32 " \
        "{%0,%1,%2,%3}, {%4,%5,%6,%7}, {%8,%9}, {%0,%1,%2,%3};" \
        : "+f"((cr)[0]), "+f"((cr)[1]), "+f"((cr)[2]), "+f"((cr)[3]) \
        : "r"((a)[0]), "r"((a)[1]), "r"((a)[2]), "r"((a)[3]), \
          "r"((b)[0]), "r"((b)[1]))

#define CP_ASYNC8(dst_smem, src_ptr, sz) \
    asm volatile("cp.async.ca.shared.global [%0], [%1], 8, %2;" \
        :: "r"(dst_smem), "l"(src_ptr), "r"(sz))
#define CP_COMMIT() asm volatile("cp.async.commit_group;" ::: "memory")
#define CP_WAIT0()  asm volatile("cp.async.wait_group 0;" ::: "memory")

// ---------------- CSR build --------------------------------------------------
__global__ void zero_k() {
    int i = blockIdx.x * blockDim.x + threadIdx.x;
    if (i < Nn) { g_cnt[i] = 0; g_cur[i] = 0; }
}

__global__ void count_k(const int* __restrict__ edges) {
    int i = blockIdx.x * blockDim.x + threadIdx.x;
    if (i >= Ee + Nn) return;
    int dst = (i < Ee) ? edges[Ee + i] : (i - Ee);
    atomicAdd(&g_cnt[dst], 1);
}

__global__ void scan1_k() {
    __shared__ int sh[256];
    int tid = threadIdx.x;
    int i = blockIdx.x * 256 + tid;
    int v = (i < Nn) ? g_cnt[i] : 0;
    sh[tid] = v;
    __syncthreads();
    #pragma unroll
    for (int off = 1; off < 256; off <<= 1) {
        int t = (tid >= off) ? sh[tid - off] : 0;
        __syncthreads();
        sh[tid] += t;
        __syncthreads();
    }
    if (i <= Nn) g_rowptr[i] = sh[tid] - v;
    if (tid == 255) g_bsum[blockIdx.x] = sh[255];
}

__global__ void scan2_k(int nblk) {
    __shared__ int sh[256];
    int tid = threadIdx.x;
    int v = (tid < nblk) ? g_bsum[tid] : 0;
    sh[tid] = v;
    __syncthreads();
    #pragma unroll
    for (int off = 1; off < 256; off <<= 1) {
        int t = (tid >= off) ? sh[tid - off] : 0;
        __syncthreads();
        sh[tid] += t;
        __syncthreads();
    }
    if (tid < nblk) g_bsum[tid] = sh[tid] - v;
    if (tid == 255) g_rowptr[Nn] = sh[255];
}

__global__ void scan3_k() {
    int i = blockIdx.x * 256 + threadIdx.x;
    if (i < Nn) g_rowptr[i] += g_bsum[blockIdx.x];
}

__global__ void fill_k(const int* __restrict__ edges) {
    int i = blockIdx.x * blockDim.x + threadIdx.x;
    if (i >= Ee + Nn) return;
    int src, dst;
    if (i < Ee) { src = edges[i]; dst = edges[Ee + i]; }
    else        { src = dst = i - Ee; }
    int p = g_rowptr[dst] + atomicAdd(&g_cur[dst], 1);
    g_csrc[p] = src;
}

// ---------------- bf16 split mma GEMM (R13 form, lda-parameterized) ---------
// C[M,302](stride HS) = A[M,302](stride lda) @ theta[302,302]^T.
// CTA tile 128x128x16, cp.async double-buffered, 48KB static smem (2 CTA/SM).
// 8 warps = 2(m) x 4(n); warp tile 64x32. m16n8k16, 3-term hi/lo split.
// Fully-OOB n-warps skip MMA. Epilogue fuses attention dots (aliased smem).
#define BMt 128
#define BNt 128
#define BKt 16
#define SWd 24
#define NIT 19
#define STGF (BMt * SWd)

__global__ __launch_bounds__(256, 2) void gemm_mma_k(const float* __restrict__ A,
                                                     int lda,
                                                     const float* __restrict__ W,
                                                     float* __restrict__ C,
                                                     const float* __restrict__ att_s,
                                                     const float* __restrict__ att_d) {
    __shared__ float pool[4 * STGF];   // 49152 B; epilogue aliases
    float* SA = pool;
    float* SW = pool + 2 * STGF;

    int tid = threadIdx.x;
    int wid = tid >> 5, lane = tid & 31;
    int g = lane >> 2, t = lane & 3;
    int m0 = blockIdx.y * BMt, n0 = blockIdx.x * BNt;
    int wm = (wid >> 2) * 64;
    int wn = (wid & 3) * 32;
    const bool active = (n0 + wn) < Dd;

    float c[4][4][4];
    #pragma unroll
    for (int i = 0; i < 4; i++)
        #pragma unroll
        for (int j = 0; j < 4; j++)
            #pragma unroll
            for (int f = 0; f < 4; f++) c[i][j][f] = 0.f;

    int srow = tid >> 3;
    int sc2  = tid & 7;

    auto stage = [&](int s, int k0) {
        #pragma unroll
        for (int e = 0; e < 4; e++) {
            int row = srow + e * 32;
            int gm = m0 + row, gk = k0 + 2 * sc2;
            bool ok = (gm < Nn) && (gk < Dd);
            const float* src = ok ? (A + (size_t)gm * lda + gk) : A;
            uint32_t dst = (uint32_t)__cvta_generic_to_shared(&SA[s * STGF + row * SWd + 2 * sc2]);
            CP_ASYNC8(dst, src, ok ? 8u : 0u);
        }
        #pragma unroll
        for (int e = 0; e < 4; e++) {
            int row = srow + e * 32;
            int gn = n0 + row, gk = k0 + 2 * sc2;
            bool ok = (gn < Dd) && (gk < Dd);
            const float* src = ok ? (W + (size_t)gn * Dd + gk) : W;
            uint32_t dst = (uint32_t)__cvta_generic_to_shared(&SW[s * STGF + row * SWd + 2 * sc2]);
            CP_ASYNC8(dst, src, ok ? 8u : 0u);
        }
    };

    stage(0, 0);
    CP_COMMIT();

    for (int it = 0; it < NIT; it++) {
        CP_WAIT0();
        __syncthreads();
        if (it + 1 < NIT) {
            stage((it + 1) & 1, (it + 1) * BKt);
            CP_COMMIT();
        }

        if (active) {
            const float* sa = SA + (it & 1) * STGF;
            const float* sw = SW + (it & 1) * STGF;

            uint32_t bh[4][2], bl[4][2];
            #pragma unroll
            for (int nt = 0; nt < 4; nt++) {
                int nr = wn + nt * 8 + g;
                float2 b0 = *(const float2*)&sw[nr * SWd + 2 * t];
                float2 b1 = *(const float2*)&sw[nr * SWd + 2 * t + 8];
                uint32_t h0 = packbf(b0.x, b0.y);
                uint32_t h1 = packbf(b1.x, b1.y);
                bh[nt][0] = h0;
                bh[nt][1] = h1;
                bl[nt][0] = packbf(b0.x - bflo(h0), b0.y - bfhi(h0));
                bl[nt][1] = packbf(b1.x - bflo(h1), b1.y - bfhi(h1));
            }
            #pragma unroll
            for (int mt = 0; mt < 4; mt++) {
                int mr = wm + mt * 16 + g;
                float2 A0 = *(const float2*)&sa[mr * SWd + 2 * t];
                float2 A1 = *(const float2*)&sa[(mr + 8) * SWd + 2 * t];
                float2 A2 = *(const float2*)&sa[mr * SWd + 2 * t + 8];
                float2 A3 = *(const float2*)&sa[(mr + 8) * SWd + 2 * t + 8];
                uint32_t ah[4], al[4];
                ah[0] = packbf(A0.x, A0.y);
                ah[1] = packbf(A1.x, A1.y);
                ah[2] = packbf(A2.x, A2.y);
                ah[3] = packbf(A3.x, A3.y);
                al[0] = packbf(A0.x - bflo(ah[0]), A0.y - bfhi(ah[0]));
                al[1] = packbf(A1.x - bflo(ah[1]), A1.y - bfhi(ah[1]));
                al[2] = packbf(A2.x - bflo(ah[2]), A2.y - bfhi(ah[2]));
                al[3] = packbf(A3.x - bflo(ah[3]), A3.y - bfhi(ah[3]));
                #pragma unroll
                for (int nt = 0; nt < 4; nt++) {
                    MMA_BF16(c[mt][nt], ah, bh[nt]);
                    MMA_BF16(c[mt][nt], ah, bl[nt]);
                    MMA_BF16(c[mt][nt], al, bh[nt]);
                }
            }
        }
    }

    // epilogue: alias stage buffers for attention vectors + partial sums
    __syncthreads();
    float* s_as  = pool;
    float* s_ad  = pool + 128;
    float* s_pas = pool + 256;
    float* s_pad = pool + 768;
    if (tid < 128) {
        int cidx = n0 + tid;
        s_as[tid] = (cidx < Dd) ? att_s[cidx] : 0.f;
        s_ad[tid] = (cidx < Dd) ? att_d[cidx] : 0.f;
    }
    __syncthreads();

    #pragma unroll
    for (int mt = 0; mt < 4; mt++) {
        int row = m0 + wm + mt * 16 + g;
        float ps = 0.f, pd = 0.f, qs = 0.f, qd = 0.f;
        #pragma unroll
        for (int nt = 0; nt < 4; nt++) {
            int cn = wn + nt * 8 + 2 * t;
            int col = n0 + cn;
            if (col < Dd) {
                if (row < Nn)
                    *(float2*)(C + (size_t)row * HS + col) =
                        make_float2(c[mt][nt][0], c[mt][nt][1]);
                if (row + 8 < Nn)
                    *(float2*)(C + (size_t)(row + 8) * HS + col) =
                        make_float2(c[mt][nt][2], c[mt][nt][3]);
            }
            float a0 = s_as[cn], a1 = s_as[cn + 1];
            float d0 = s_ad[cn], d1 = s_ad[cn + 1];
            ps += c[mt][nt][0] * a0 + c[mt][nt][1] * a1;
            pd += c[mt][nt][0] * d0 + c[mt][nt][1] * d1;
            qs += c[mt][nt][2] * a0 + c[mt][nt][3] * a1;
            qd += c[mt][nt][2] * d0 + c[mt][nt][3] * d1;
        }
        #pragma unroll
        for (int o = 1; o <= 2; o <<= 1) {
            ps += __shfl_xor_sync(0xffffffffu, ps, o);
            pd += __shfl_xor_sync(0xffffffffu, pd, o);
            qs += __shfl_xor_sync(0xffffffffu, qs, o);
            qd += __shfl_xor_sync(0xffffffffu, qd, o);
        }
        if (t == 0) {
            int i1 = wm + mt * 16 + g;
            int nw = wid & 3;
            s_pas[nw * 128 + i1] = ps;  s_pad[nw * 128 + i1] = pd;
            s_pas[nw * 128 + i1 + 8] = qs;  s_pad[nw * 128 + i1 + 8] = qd;
        }
    }
    __syncthreads();
    if (tid < 128) {
        int row = m0 + tid;
        if (row < Nn)
            g_asp[blockIdx.x][row] = s_pas[tid] + s_pas[128 + tid] +
                                     s_pas[256 + tid] + s_pas[384 + tid];
    } else {
        int i = tid - 128;
        int row = m0 + i;
        if (row < Nn)
            g_adp[blockIdx.x][row] = s_pad[i] + s_pad[128 + i] +
                                     s_pad[256 + i] + s_pad[384 + i];
    }
}

__global__ void combine_k() {
    int i = blockIdx.x * blockDim.x + threadIdx.x;
    if (i < Nn) {
        g_as[i] = g_asp[0][i] + g_asp[1][i] + g_asp[2][i];
        g_ad[i] = g_adp[0][i] + g_adp[1][i] + g_adp[2][i];
    }
}

// ---------------- fused edge softmax + aggregation (warp per dst) -----------
// Vectorized gather: per src row 2x LDG.128 + 2 scalar (rows 16B-aligned, HS).
// Lane owns cols {4L..4L+3, 128+4L..128+4L+3, 256+L, 288+L(L<14)}.
// mode 1 additionally computes the pooling score g_s.
__global__ void agg_k(const float* __restrict__ h,
                      const float* __restrict__ bias,
                      float* __restrict__ outp,
                      const int* __restrict__ batch, int mode) {
    int w = (blockIdx.x * blockDim.x + threadIdx.x) >> 5;
    int lane = threadIdx.x & 31;
    if (w >= Nn) return;
    int beg = g_rowptr[w], end = g_rowptr[w + 1];
    float ad = g_ad[w];

    float m = -3.4e38f, den = 0.f;
    for (int j = beg + lane; j < end; j += 32) {
        float e = lrelu(g_as[g_csrc[j]] + ad);
        if (e > m) { den = den * __expf(m - e) + 1.f; m = e; }
        else den += __expf(e - m);
    }
    #pragma unroll
    for (int o = 16; o; o >>= 1) {
        float mo = __shfl_xor_sync(0xffffffffu, m, o);
        float eo = __shfl_xor_sync(0xffffffffu, den, o);
        float mn = fmaxf(m, mo);
        den = den * __expf(m - mn) + eo * __expf(mo - mn);
        m = mn;
    }
    float inv = 1.f / den;

    float4 a0 = make_float4(0.f, 0.f, 0.f, 0.f);
    float4 a1 = make_float4(0.f, 0.f, 0.f, 0.f);
    float t0 = 0.f, t1 = 0.f;
    bool tl = lane < 14;

    for (int base = beg; base < end; base += 32) {
        int j = base + lane;
        float wt = 0.f; int src = 0;
        if (j < end) {
            src = g_csrc[j];
            wt = __expf(lrelu(g_as[src] + ad) - m) * inv;
        }
        int cnt = min(32, end - base);
        for (int u = 0; u < cnt; u++) {
            float wu = __shfl_sync(0xffffffffu, wt, u);
            int   su = __shfl_sync(0xffffffffu, src, u);
            const float* hr = h + (size_t)su * HS;
            const float4* hr4 = (const float4*)hr;
            float4 v0 = hr4[lane];
            float4 v1 = hr4[32 + lane];
            float u0 = hr[256 + lane];
            float u1 = tl ? hr[288 + lane] : 0.f;
            a0.x += wu * v0.x; a0.y += wu * v0.y; a0.z += wu * v0.z; a0.w += wu * v0.w;
            a1.x += wu * v1.x; a1.y += wu * v1.y; a1.z += wu * v1.z; a1.w += wu * v1.w;
            t0 += wu * u0;
            t1 += wu * u1;
        }
    }

    int c0 = 4 * lane, c1 = 128 + 4 * lane;
    float4 b0 = *(const float4*)(bias + c0);
    float4 b1 = *(const float4*)(bias + c1);
    float bt0 = bias[256 + lane];
    float bt1 = tl ? bias[288 + lane] : 0.f;

    float4 r0, r1;
    r0.x = fmaxf(a0.x + b0.x, 0.f); r0.y = fmaxf(a0.y + b0.y, 0.f);
    r0.z = fmaxf(a0.z + b0.z, 0.f); r0.w = fmaxf(a0.w + b0.w, 0.f);
    r1.x = fmaxf(a1.x + b1.x, 0.f); r1.y = fmaxf(a1.y + b1.y, 0.f);
    r1.z = fmaxf(a1.z + b1.z, 0.f); r1.w = fmaxf(a1.w + b1.w, 0.f);
    float rt0 = fmaxf(t0 + bt0, 0.f);
    float rt1 = fmaxf(t1 + bt1, 0.f);

    float* orow = outp + (size_t)w * HS;
    *(float4*)(orow + c0) = r0;
    *(float4*)(orow + c1) = r1;
    orow[256 + lane] = rt0;
    if (tl) orow[288 + lane] = rt1;

    if (mode == 1) {
        int b = batch[w];
        const float* qr = g_qp + (size_t)b * HS;
        const float4* qr4 = (const float4*)qr;
        float4 q0 = qr4[lane], q1 = qr4[32 + lane];
        float s = r0.x * q0.x + r0.y * q0.y + r0.z * q0.z + r0.w * q0.w
                + r1.x * q1.x + r1.y * q1.y + r1.z * q1.z + r1.w * q1.w
                + rt0 * qr[256 + lane]
                + (tl ? rt1 * qr[288 + lane] : 0.f);
        #pragma unroll
        for (int o = 16; o; o >>= 1) s += __shfl_xor_sync(0xffffffffu, s, o);
        if (lane == 0) g_s[w] = s * 0.04082482904638630f;  // 1/sqrt(600)
    }
}

// ---------------- qp = query @ attW  [B,HS] ---------------------------------
__global__ void qp_k(const float* __restrict__ query, const float* __restrict__ attW) {
    int b = blockIdx.x;
    __shared__ float q[Qq];
    for (int i = threadIdx.x; i < Qq; i += blockDim.x) q[i] = query[(size_t)b * Qq + i];
    __syncthreads();
    for (int d = threadIdx.x; d < HS; d += blockDim.x) {
        float acc = 0.f;
        if (d < Dd)
            for (int qi = 0; qi < Qq; qi++) acc += q[qi] * attW[(size_t)qi * Dd + d];
        g_qp[b * HS + d] = acc;   // pad cols 302,303 with 0
    }
}

// ---------------- block-per-graph softmax pooling (batch is sorted) ---------
__global__ __launch_bounds__(256) void pool_k(const float* __restrict__ h,
                                              const int* __restrict__ batch) {
    int b = blockIdx.x;
    int tid = threadIdx.x, wid = tid >> 5, lane = tid & 31;
    __shared__ float red[256];
    __shared__ float s_acc[8][304];
    int start = lower_bound_i(batch, Nn, b);
    int end   = lower_bound_i(batch, Nn, b + 1);

    float m = -3.4e38f;
    for (int n = start + tid; n < end; n += 256) m = fmaxf(m, g_s[n]);
    red[tid] = m; __syncthreads();
    for (int o = 128; o; o >>= 1) { if (tid < o) red[tid] = fmaxf(red[tid], red[tid + o]); __syncthreads(); }
    m = red[0]; __syncthreads();

    float ds = 0.f;
    for (int n = start + tid; n < end; n += 256) ds += __expf(g_s[n] - m);
    red[tid] = ds; __syncthreads();
    for (int o = 128; o; o >>= 1) { if (tid < o) red[tid] += red[tid + o]; __syncthreads(); }
    float total = red[0];
    float inv = (total > 0.f) ? 1.f / total : 0.f;
    __syncthreads();

    float4 a0 = make_float4(0.f, 0.f, 0.f, 0.f);
    float4 a1 = make_float4(0.f, 0.f, 0.f, 0.f);
    float t0 = 0.f, t1 = 0.f;
    bool tl = lane < 14;
    for (int r = start + wid; r < end; r += 8) {
        float wt = __expf(g_s[r] - m) * inv;
        const float* hr = h + (size_t)r * HS;
        const float4* hr4 = (const float4*)hr;
        float4 v0 = hr4[lane];
        float4 v1 = hr4[32 + lane];
        float u0 = hr[256 + lane];
        float u1 = tl ? hr[288 + lane] : 0.f;
        a0.x += wt * v0.x; a0.y += wt * v0.y; a0.z += wt * v0.z; a0.w += wt * v0.w;
        a1.x += wt * v1.x; a1.y += wt * v1.y; a1.z += wt * v1.z; a1.w += wt * v1.w;
        t0 += wt * u0;
        t1 += wt * u1;
    }
    int c0 = 4 * lane;
    *(float4*)&s_acc[wid][c0] = a0;
    *(float4*)&s_acc[wid][128 + c0] = a1;
    s_acc[wid][256 + lane] = t0;
    if (tl) s_acc[wid][288 + lane] = t1;
    __syncthreads();
    for (int cc = tid; cc < Dd; cc += 256) {
        float v = 0.f;
        #pragma unroll
        for (int u = 0; u < 8; u++) v += s_acc[u][cc];
        g_pool[b * Dd + cc] = v > 0.f ? v : 0.f;   // ReLU fused
    }
}

// ---------------- final: out = relu(pooled) @ lin_w^T + lin_b ---------------
#define FINAL_SMEM (128 * 303 * 4)
__global__ __launch_bounds__(512) void final_k(const float* __restrict__ lin_w,
                                               const float* __restrict__ lin_b,
                                               float* __restrict__ out) {
    extern __shared__ float ps[];   // [128][303]
    int tid = threadIdx.x;
    for (int i = tid; i < Bb * Dd; i += 512) {
        int bb = i / Dd, k = i - bb * Dd;
        ps[bb * 303 + k] = g_pool[i];
    }
    __syncthreads();
    int w = tid >> 5, lane = tid & 31;
    int c = blockIdx.x * 16 + w;
    const float* wr = lin_w + (size_t)c * Dd;
    float a0 = 0.f, a1 = 0.f, a2 = 0.f, a3 = 0.f;
    for (int k = 0; k < Dd; k++) {
        float wv = wr[k];
        a0 += wv * ps[lane * 303 + k];
        a1 += wv * ps[(lane + 32) * 303 + k];
        a2 += wv * ps[(lane + 64) * 303 + k];
        a3 += wv * ps[(lane + 96) * 303 + k];
    }
    float lb = lin_b[c];
    out[(size_t)lane * Cc + c]        = a0 + lb;
    out[(size_t)(lane + 32) * Cc + c] = a1 + lb;
    out[(size_t)(lane + 64) * Cc + c] = a2 + lb;
    out[(size_t)(lane + 96) * Cc + c] = a3 + lb;
}

// ---------------- launch -----------------------------------------------------
extern "C" void kernel_launch(void* const* d_in, const int* in_sizes, int n_in,
                              void* d_out, int out_size) {
    const float* x        = (const float*)d_in[0];
    const int*   edges    = (const int*)  d_in[1];
    const float* query    = (const float*)d_in[2];
    const int*   batch    = (const int*)  d_in[3];
    const float* theta    = (const float*)d_in[4];
    const float* att_src  = (const float*)d_in[5];
    const float* att_dst  = (const float*)d_in[6];
    const float* gat_bias = (const float*)d_in[7];
    const float* attW     = (const float*)d_in[8];
    const float* lin_w    = (const float*)d_in[9];
    const float* lin_b    = (const float*)d_in[10];
    float* out = (float*)d_out;

    float *p_h, *p_o;
    cudaGetSymbolAddress((void**)&p_h, g_h);
    cudaGetSymbolAddress((void**)&p_o, g_o);

    cudaFuncSetAttribute(final_k, cudaFuncAttributeMaxDynamicSharedMemorySize, FINAL_SMEM);

    dim3 ggrid((Dd + BNt - 1) / BNt, (Nn + BMt - 1) / BMt);
    int wgrid = (Nn * 32 + 255) / 256;
    int cgrid = (Nn + 255) / 256;
    int sblk = (Nn + 255) / 256;

    // CSR build (parallel scan)
    zero_k<<<cgrid, 256>>>();
    count_k<<<(Ee + Nn + 255) / 256, 256>>>(edges);
    scan1_k<<<sblk, 256>>>();
    scan2_k<<<1, 256>>>(sblk);
    scan3_k<<<sblk, 256>>>();
    fill_k<<<(Ee + Nn + 255) / 256, 256>>>(edges);

    // layer 1 (input = raw x, stride Dd)
    gemm_mma_k<<<ggrid, 256>>>(x, Dd, theta, p_h, att_src, att_dst);
    combine_k<<<cgrid, 256>>>();
    agg_k<<<wgrid, 256>>>(p_h, gat_bias, p_o, batch, 0);
    // layer 2 (input = g_o, stride HS)
    gemm_mma_k<<<ggrid, 256>>>(p_o, HS, theta, p_h, att_src, att_dst);
    combine_k<<<cgrid, 256>>>();
    agg_k<<<wgrid, 256>>>(p_h, gat_bias, p_o, batch, 0);
    // layer 3 (fuses pooling score)
    gemm_mma_k<<<ggrid, 256>>>(p_o, HS, theta, p_h, att_src, att_dst);
    combine_k<<<cgrid, 256>>>();
    qp_k<<<Bb, 384>>>(query, attW);
    agg_k<<<wgrid, 256>>>(p_h, gat_bias, p_o, batch, 1);

    pool_k<<<Bb, 256>>>(p_o, batch);
    final_k<<<Cc / 16, 512, FINAL_SMEM>>>(lin_w, lin_b, out);
}